// round 12
// baseline (speedup 1.0000x reference)
#include <cuda_runtime.h>

#define N_ROWS 8000
#define D 9
#define N4 2000            // N_ROWS / 4 (float4 columns)
#define OUT_TPB 256
#define ROWS_PER_BLK 64
#define CHUNK 64           // rows per prologue block
#define NB1 125            // 125 * 64 = 8000
#define K1_TPB 64

// Scratch (device globals — no allocation allowed)
__device__ float d_delta[N_ROWS];   // within-chunk inclusive cumsum of (s1-s2)
__device__ float d_csum[NB1];       // per-chunk totals
__device__ float d_spref[NB1];      // exclusive prefix of chunk totals
__device__ float d_g[N_ROWS];
__device__ float d_h[N_ROWS];
__device__ unsigned int d_tick;     // arrival ticket (self-resetting)

// ---------------------------------------------------------------------------
// K1: parallel rowstats + local scans (125 blocks); last-arriving block scans
// the 125 chunk totals -> d_spref. Triggers PDL completion after final writes.
// ---------------------------------------------------------------------------
__global__ void __launch_bounds__(K1_TPB)
k_pro(const float* __restrict__ x,
      const float* __restrict__ a1, const float* __restrict__ c1,
      const float* __restrict__ a2, const float* __restrict__ c2,
      const float* __restrict__ wf1, const float* __restrict__ bf1,
      const float* __restrict__ wf2, const float* __restrict__ bf2)
{
    __shared__ float s_w0tot;
    __shared__ float swt[2];
    __shared__ int   s_last;

    const int t = threadIdx.x;
    const int b = blockIdx.x;
    const unsigned lane = t & 31;
    const int w = t >> 5;

    // ---- rowstats: one row per thread ----
    const int r = b * CHUNK + t;
    const float inv1 = 1.0f / __ldg(a1);
    const float inv2 = 1.0f / __ldg(a2);
    const float k1 = -__ldg(c1) * inv1;
    const float k2 = -__ldg(c2) * inv2;
    float s1 = 0.f, s2 = 0.f;
    float f1 = __ldg(bf1), f2 = __ldg(bf2);
#pragma unroll
    for (int d = 0; d < D; d++) {
        float xv = __ldg(&x[r * D + d]);
        float u1 = fmaf(xv, inv1, k1);
        float u2 = fmaf(xv, inv2, k2);
        s1 = fmaf(u1, u1, s1);
        s2 = fmaf(u2, u2, s2);
        f1 = fmaf(xv, __ldg(&wf1[d]), f1);
        f2 = fmaf(xv, __ldg(&wf2[d]), f2);
    }
    d_g[r] = f1 - f2;
    d_h[r] = f2;

    // ---- within-chunk inclusive cumsum (2 warps) ----
    float v = s1 - s2;
#pragma unroll
    for (int o = 1; o < 32; o <<= 1) {
        float n = __shfl_up_sync(0xffffffff, v, o);
        if (lane >= o) v += n;
    }
    if (t == 31) s_w0tot = v;
    __syncthreads();
    if (w == 1) v += s_w0tot;
    d_delta[r] = v;
    if (t == CHUNK - 1) d_csum[b] = v;

    __threadfence();                 // publish before arriving
    __syncthreads();
    if (t == 0) {
        unsigned tk = atomicAdd(&d_tick, 1u);
        s_last = (tk == NB1 - 1u);
    }
    __syncthreads();
    if (!s_last) {
        cudaTriggerProgrammaticLaunchCompletion();
        return;
    }

    // ---- last block: tiny two-level scan of 125 chunk totals -> d_spref ----
    __threadfence();                 // acquire
    float c0  = (t < NB1)      ? d_csum[t]      : 0.0f;
    float c1v = (t + 64 < NB1) ? d_csum[t + 64] : 0.0f;

    float a = c0;                    // scan chunks 0..63
#pragma unroll
    for (int o = 1; o < 32; o <<= 1) {
        float n = __shfl_up_sync(0xffffffff, a, o);
        if (lane >= o) a += n;
    }
    if (lane == 31) swt[w] = a;
    __syncthreads();
    if (w == 1) a += swt[0];
    float total64 = swt[0] + swt[1];
    d_spref[t] = a - c0;             // exclusive prefix for chunk t
    __syncthreads();

    float bsc = c1v;                 // scan chunks 64..124
#pragma unroll
    for (int o = 1; o < 32; o <<= 1) {
        float n = __shfl_up_sync(0xffffffff, bsc, o);
        if (lane >= o) bsc += n;
    }
    if (lane == 31) swt[w] = bsc;
    __syncthreads();
    if (w == 1) bsc += swt[0];
    if (t + 64 < NB1)
        d_spref[t + 64] = total64 + bsc - c1v;

    if (t == 0) d_tick = 0;          // self-reset for graph replays
    __threadfence();
    __syncthreads();
    cudaTriggerProgrammaticLaunchCompletion();
}

// ---------------------------------------------------------------------------
// K2: out[i,j] = h[i] + g[i]*w1bar[j], w1bar inline (amortized over 64 rows):
//   w1bar[j] = 1/(1+exp(spref[j>>6 of column] + d_delta[j]))
// Low-reg R5 body shape: no smem, direct g/h broadcast loads, __stcs.
// PDL: waits on k_pro's completion before touching its outputs.
// ---------------------------------------------------------------------------
__global__ void __launch_bounds__(OUT_TPB)
k_outer(float* __restrict__ out)
{
    cudaGridDependencySynchronize();

    const int j4 = blockIdx.x * OUT_TPB + threadIdx.x;
    if (j4 >= N4) return;

    const float pre = __ldg(&d_spref[j4 >> 4]);          // (j4*4)>>6
    const float4 dl = reinterpret_cast<const float4*>(d_delta)[j4];
    float4 w4;
    w4.x = 1.0f / (1.0f + __expf(pre + dl.x));
    w4.y = 1.0f / (1.0f + __expf(pre + dl.y));
    w4.z = 1.0f / (1.0f + __expf(pre + dl.z));
    w4.w = 1.0f / (1.0f + __expf(pre + dl.w));

    const int i0 = blockIdx.y * ROWS_PER_BLK;
    float4* o4 = reinterpret_cast<float4*>(out);

#pragma unroll 16
    for (int k = 0; k < ROWS_PER_BLK; k++) {
        const int i = i0 + k;
        const float gv = d_g[i];
        const float hv = d_h[i];
        float4 o;
        o.x = fmaf(gv, w4.x, hv);
        o.y = fmaf(gv, w4.y, hv);
        o.z = fmaf(gv, w4.z, hv);
        o.w = fmaf(gv, w4.w, hv);
        __stcs(&o4[(size_t)i * N4 + j4], o);
    }
}

// ---------------------------------------------------------------------------
extern "C" void kernel_launch(void* const* d_in, const int* in_sizes, int n_in,
                              void* d_out, int out_size)
{
    const float* x   = (const float*)d_in[0];
    const float* a1  = (const float*)d_in[1];
    const float* c1  = (const float*)d_in[2];
    const float* a2  = (const float*)d_in[3];
    const float* c2  = (const float*)d_in[4];
    const float* wf1 = (const float*)d_in[5];
    const float* bf1 = (const float*)d_in[6];
    const float* wf2 = (const float*)d_in[7];
    const float* bf2 = (const float*)d_in[8];
    float* out = (float*)d_out;

    k_pro<<<NB1, K1_TPB>>>(x, a1, c1, a2, c2, wf1, bf1, wf2, bf2);

    // k_outer with programmatic dependent launch (overlaps launch with k_pro tail)
    cudaLaunchConfig_t cfg = {};
    cfg.gridDim  = dim3((N4 + OUT_TPB - 1) / OUT_TPB, N_ROWS / ROWS_PER_BLK);  // (8, 125)
    cfg.blockDim = dim3(OUT_TPB, 1, 1);
    cudaLaunchAttribute attr[1];
    attr[0].id = cudaLaunchAttributeProgrammaticStreamSerialization;
    attr[0].val.programmaticStreamSerializationAllowed = 1;
    cfg.attrs = attr;
    cfg.numAttrs = 1;
    cudaLaunchKernelEx(&cfg, k_outer, out);
}

// round 13
// speedup vs baseline: 1.1952x; 1.1952x over previous
#include <cuda_runtime.h>

#define N_ROWS 8000
#define D 9
#define N4 2000            // N_ROWS / 4 (float4 columns)
#define OUT_TPB 256
#define ROWS_PER_BLK 16
#define CHUNK 64           // rows per prologue block
#define NB1 125            // 125 * 64 = 8000
#define K1_TPB 64

// Scratch (device globals — no allocation allowed)
__device__ float d_csum[NB1];       // per-chunk totals
__device__ float d_delta[N_ROWS];   // within-chunk inclusive cumsum
__device__ float d_w1bar[N_ROWS];
__device__ float d_g[N_ROWS];
__device__ float d_h[N_ROWS];

// ---------------------------------------------------------------------------
// K1: rowstats + within-chunk scan. Pure dataflow — no atomics, no fences.
// ---------------------------------------------------------------------------
__global__ void __launch_bounds__(K1_TPB)
k_pro(const float* __restrict__ x,
      const float* __restrict__ a1, const float* __restrict__ c1,
      const float* __restrict__ a2, const float* __restrict__ c2,
      const float* __restrict__ wf1, const float* __restrict__ bf1,
      const float* __restrict__ wf2, const float* __restrict__ bf2)
{
    __shared__ float s_w0tot;

    const int t = threadIdx.x;
    const int b = blockIdx.x;
    const unsigned lane = t & 31;
    const int w = t >> 5;

    const int r = b * CHUNK + t;
    const float inv1 = 1.0f / __ldg(a1);
    const float inv2 = 1.0f / __ldg(a2);
    const float k1 = -__ldg(c1) * inv1;
    const float k2 = -__ldg(c2) * inv2;
    float s1 = 0.f, s2 = 0.f;
    float f1 = __ldg(bf1), f2 = __ldg(bf2);
#pragma unroll
    for (int d = 0; d < D; d++) {
        float xv = __ldg(&x[r * D + d]);
        float u1 = fmaf(xv, inv1, k1);
        float u2 = fmaf(xv, inv2, k2);
        s1 = fmaf(u1, u1, s1);
        s2 = fmaf(u2, u2, s2);
        f1 = fmaf(xv, __ldg(&wf1[d]), f1);
        f2 = fmaf(xv, __ldg(&wf2[d]), f2);
    }
    d_g[r] = f1 - f2;
    d_h[r] = f2;

    // within-chunk inclusive cumsum (2 warps)
    float v = s1 - s2;
#pragma unroll
    for (int o = 1; o < 32; o <<= 1) {
        float n = __shfl_up_sync(0xffffffff, v, o);
        if (lane >= o) v += n;
    }
    if (t == 31) s_w0tot = v;
    __syncthreads();
    if (w == 1) v += s_w0tot;
    d_delta[r] = v;
    if (t == CHUNK - 1) d_csum[b] = v;
}

// ---------------------------------------------------------------------------
// K2: each block reduces its own prefix over csum[0..b-1] (L2-hot), then:
//   w1bar[r] = 1/(1+exp(pref + d_delta[r]))
// Kernel boundary (PDL-ordered) provides all synchronization.
// ---------------------------------------------------------------------------
__global__ void __launch_bounds__(K1_TPB)
k_apply()
{
    cudaGridDependencySynchronize();

    __shared__ float swt[2];

    const int t = threadIdx.x;
    const int b = blockIdx.x;
    const unsigned lane = t & 31;
    const int w = t >> 5;

    float s = 0.0f;
    if (t < b)      s += d_csum[t];
    if (t + 64 < b) s += d_csum[t + 64];
#pragma unroll
    for (int o = 16; o > 0; o >>= 1)
        s += __shfl_down_sync(0xffffffff, s, o);
    if (lane == 0) swt[w] = s;
    __syncthreads();
    const float pref = swt[0] + swt[1];

    const int r = b * CHUNK + t;
    const float run = pref + d_delta[r];        // S1[r] - S2[r]
    d_w1bar[r] = 1.0f / (1.0f + __expf(run));
}

// ---------------------------------------------------------------------------
// K3: out[i,j] = h[i] + g[i]*w1bar[j] — the proven 37.4 us configuration:
// 16 rows/block, 4000 blocks, 26 regs, no smem, streaming float4 stores.
// ---------------------------------------------------------------------------
__global__ void k_outer(float* __restrict__ out)
{
    cudaGridDependencySynchronize();

    int j4 = blockIdx.x * OUT_TPB + threadIdx.x;
    if (j4 >= N4) return;

    float4 w4 = reinterpret_cast<const float4*>(d_w1bar)[j4];
    int i0 = blockIdx.y * ROWS_PER_BLK;
    float4* o4 = reinterpret_cast<float4*>(out);

#pragma unroll
    for (int k = 0; k < ROWS_PER_BLK; k++) {
        int i = i0 + k;
        float gv = d_g[i];
        float hv = d_h[i];
        float4 o;
        o.x = fmaf(gv, w4.x, hv);
        o.y = fmaf(gv, w4.y, hv);
        o.z = fmaf(gv, w4.z, hv);
        o.w = fmaf(gv, w4.w, hv);
        __stcs(&o4[(size_t)i * N4 + j4], o);
    }
}

// ---------------------------------------------------------------------------
extern "C" void kernel_launch(void* const* d_in, const int* in_sizes, int n_in,
                              void* d_out, int out_size)
{
    const float* x   = (const float*)d_in[0];
    const float* a1  = (const float*)d_in[1];
    const float* c1  = (const float*)d_in[2];
    const float* a2  = (const float*)d_in[3];
    const float* c2  = (const float*)d_in[4];
    const float* wf1 = (const float*)d_in[5];
    const float* bf1 = (const float*)d_in[6];
    const float* wf2 = (const float*)d_in[7];
    const float* bf2 = (const float*)d_in[8];
    float* out = (float*)d_out;

    k_pro<<<NB1, K1_TPB>>>(x, a1, c1, a2, c2, wf1, bf1, wf2, bf2);

    cudaLaunchAttribute attr[1];
    attr[0].id = cudaLaunchAttributeProgrammaticStreamSerialization;
    attr[0].val.programmaticStreamSerializationAllowed = 1;

    // k_apply, PDL-chained behind k_pro
    cudaLaunchConfig_t cfgA = {};
    cfgA.gridDim  = dim3(NB1, 1, 1);
    cfgA.blockDim = dim3(K1_TPB, 1, 1);
    cfgA.attrs = attr;
    cfgA.numAttrs = 1;
    cudaLaunchKernelEx(&cfgA, k_apply);

    // k_outer, PDL-chained behind k_apply
    cudaLaunchConfig_t cfgO = {};
    cfgO.gridDim  = dim3((N4 + OUT_TPB - 1) / OUT_TPB, N_ROWS / ROWS_PER_BLK);  // (8, 500)
    cfgO.blockDim = dim3(OUT_TPB, 1, 1);
    cfgO.attrs = attr;
    cfgO.numAttrs = 1;
    cudaLaunchKernelEx(&cfgO, k_outer, out);
}